// round 16
// baseline (speedup 1.0000x reference)
#include <cuda_runtime.h>

typedef unsigned long long u64;
#define FULLMASK 0xffffffffu

// ---- f32x2 packed helpers (sm_103a) ------------------------------------
__device__ __forceinline__ u64 pk(float lo, float hi){
    u64 r; asm("mov.b64 %0, {%1, %2};" : "=l"(r) : "f"(lo), "f"(hi)); return r;
}
__device__ __forceinline__ void unpk(u64 v, float &lo, float &hi){
    asm("mov.b64 {%0, %1}, %2;" : "=f"(lo), "=f"(hi) : "l"(v));
}
__device__ __forceinline__ u64 f2mul(u64 a, u64 b){
    u64 d; asm("mul.rn.f32x2 %0, %1, %2;" : "=l"(d) : "l"(a), "l"(b)); return d;
}
__device__ __forceinline__ u64 f2fma(u64 a, u64 b, u64 c){
    u64 d; asm("fma.rn.f32x2 %0, %1, %2, %3;" : "=l"(d) : "l"(a), "l"(b), "l"(c)); return d;
}
__device__ __forceinline__ u64 swap_slots(u64 v){
    float a, b; unpk(v, a, b); return pk(b, a);
}
__device__ __forceinline__ float2 cmul(float2 a, float2 b){
    return make_float2(a.x*b.x - a.y*b.y, a.x*b.y + a.y*b.x);
}

// Splat table (row-contiguous, 12 u64 per gate):
//   [0..2] = g00 (x,-y,+y), [3..5] = g01, [6..8] = g11, [9..11] = g10
__device__ __forceinline__ void gap2(const u64* g, u64 &X0, u64 &Y0, u64 &X1, u64 &Y1){
    u64 nX0 = f2mul(g[0], X0); nX0 = f2fma(g[1],  Y0, nX0); nX0 = f2fma(g[3], X1, nX0); nX0 = f2fma(g[4],  Y1, nX0);
    u64 nY0 = f2mul(g[0], Y0); nY0 = f2fma(g[2],  X0, nY0); nY0 = f2fma(g[3], Y1, nY0); nY0 = f2fma(g[5],  X1, nY0);
    u64 nX1 = f2mul(g[9], X0); nX1 = f2fma(g[10], Y0, nX1); nX1 = f2fma(g[6], X1, nX1); nX1 = f2fma(g[7],  Y1, nX1);
    u64 nY1 = f2mul(g[9], Y0); nY1 = f2fma(g[11], X0, nY1); nY1 = f2fma(g[6], Y1, nY1); nY1 = f2fma(g[8],  X1, nY1);
    X0 = nX0; Y0 = nY0; X1 = nX1; Y1 = nY1;
}

// One CTA per sample. 4096 amps = 256 threads x 8 f32x2-packed complex pairs.
// ALL gates are applied locally: each layer runs as 3 rounds of 4 local gates
// (3 p-bit wires via gap2 + 1 slot wire via paired-coefficient form); wires are
// re-localized between rounds by pure-permutation smem exchanges (float2
// granularity, XOR-swizzled: addr = (loc<<8) ^ tid ^ loc, loc = p*2+slot).
// sigma_1 (CNOT chain of layer 1) folds into the init parities, sigma_2 into
// exchange X3, sigma_3 into the readout parities. Zero shuffle butterflies.
//
// Layouts (wire -> bit): L1/L6: warp=w0w1w2, lane=w3..w7, p=w8w9w10, slot=w11.
// L2/L5: warp=w0w1w2 (L2) / w8w9w10 (L5-pre)... see exchange derivations:
//   X1/X4 (intra-warp): swap local quad with lane b3..b0 quad.
//   X2/X5 (CTA):        swap local quad with warp bits + lane b4.
//   X3 (CTA, sigma_2):  prefix-xor inverse, layout-preserving.
__global__ void __launch_bounds__(256, 3) qsim_kernel(
    const float* __restrict__ x,        // [B,12]
    const float* __restrict__ params,   // [3,12,3]
    const float* __restrict__ hw,       // [12]
    const float* __restrict__ hb,       // [1]
    float* __restrict__ out)            // [B]
{
    __shared__ float2 amp[4096];        // 32KB exchange buffer (swizzled)
    __shared__ float2 sG[3][12][4];     // fused RY*RZ*RY scalar gates
    __shared__ u64 sGp[2][12][12];      // splat tables for circuit layers 2,3
    __shared__ u64 sGs[6][6];           // slot-gate paired coeffs per round
    __shared__ float2 sV[12][2];        // layer-1-folded init vectors
    __shared__ float sC[12], sS[12], sHw[12], sRed[8];

    const int tid  = threadIdx.x;
    const int lane = tid & 31;
    const int warp = tid >> 5;
    const int b    = blockIdx.x;

    // ---- Stage 0: fused gates + per-sample RX angles
    if (tid < 36){
        int l = tid / 12, i = tid % 12;
        float pa = params[(l*12 + i)*3 + 0];
        float pb = params[(l*12 + i)*3 + 1];
        float pc = params[(l*12 + i)*3 + 2];
        float ca, sa, cb, sb, cc, sc;
        sincosf(0.5f*pa, &sa, &ca);
        sincosf(0.5f*pb, &sb, &cb);
        sincosf(0.5f*pc, &sc, &cc);
        float2 em = make_float2(cb, -sb);
        float2 ep = make_float2(cb,  sb);
        float ccca = cc*ca, scsa = sc*sa, ccsa = cc*sa, scca = sc*ca;
        sG[l][i][0] = make_float2( ccca*em.x - scsa*ep.x,  ccca*em.y - scsa*ep.y);
        sG[l][i][1] = make_float2(-ccsa*em.x - scca*ep.x, -ccsa*em.y - scca*ep.y);
        sG[l][i][2] = make_float2( scca*em.x + ccsa*ep.x,  scca*em.y + ccsa*ep.y);
        sG[l][i][3] = make_float2(-scsa*em.x + ccca*ep.x, -scsa*em.y + ccca*ep.y);
    } else if (tid >= 64 && tid < 76){
        int i = tid - 64;
        float s, c;
        sincosf(0.5f * x[b*12 + i], &s, &c);
        sC[i] = c; sS[i] = s;
        sHw[i] = hw[i];
    }
    __syncthreads();

    if (tid < 96){
        // splat tables for circuit layers 2 (sGp[0]) and 3 (sGp[1])
        int ll = tid / 48, r = tid % 48, i = r >> 2, e = r & 3;
        float2 g = sG[ll+1][i][e];
        int base = 3 * (e ^ (e >> 1));
        sGp[ll][i][base+0] = pk( g.x,  g.x);
        sGp[ll][i][base+1] = pk(-g.y, -g.y);
        sGp[ll][i][base+2] = pk( g.y,  g.y);
    } else if (tid >= 128 && tid < 140){
        // sV[w] = G1_w * (cos, -i sin): whole layer 1 folded into product init
        int w = tid - 128;
        float c = sC[w], s = sS[w];
        float2 g00 = sG[0][w][0], g01 = sG[0][w][1];
        float2 g10 = sG[0][w][2], g11 = sG[0][w][3];
        sV[w][0] = make_float2(g00.x*c + g01.y*s, g00.y*c - g01.x*s);
        sV[w][1] = make_float2(g10.x*c + g11.y*s, g10.y*c - g11.x*s);
    } else if (tid >= 144 && tid < 150){
        // slot-gate paired coefficients per round: (l,w) = (1,11)(1,7)(1,3)(2,3)(2,7)(2,11)
        int k = tid - 144;
        int l = (k < 3) ? 1 : 2;
        int w = (k < 3) ? (11 - 4*k) : (4*k - 9);
        float2 g00 = sG[l][w][0], g01 = sG[l][w][1];
        float2 g10 = sG[l][w][2], g11 = sG[l][w][3];
        sGs[k][0] = pk( g00.x,  g11.x);   // A
        sGs[k][1] = pk( g01.x,  g10.x);   // B
        sGs[k][2] = pk(-g00.y, -g11.y);   // A'
        sGs[k][3] = pk(-g01.y, -g10.y);   // B'
        sGs[k][4] = pk( g00.y,  g11.y);   // A2
        sGs[k][5] = pk( g01.y,  g10.y);   // B2
    }
    __syncthreads();

    // ---- Init in L1 with sigma_1 folded: amp[t] = prod_w v_w[u_w], u_w = t_w ^ t_{w-1}
    u64 X[8], Y[8];
    {
        int gt = tid ^ (tid >> 1);        // u_w for wires 0..7 at bit (7-w)
        float2 base = sV[0][(gt >> 7) & 1];
        #pragma unroll
        for (int w = 1; w < 8; w++)
            base = cmul(base, sV[w][(gt >> (7 - w)) & 1]);
        int t7 = tid & 1;
        float2 m8[2], m89[4];
        m8[0] = cmul(base, sV[8][t7]);        // u8 = p2 ^ t7 : index p2 -> sV[8][p2^t7]
        m8[1] = cmul(base, sV[8][t7 ^ 1]);
        m89[0] = cmul(m8[0], sV[9][0]); m89[1] = cmul(m8[0], sV[9][1]);
        m89[2] = cmul(m8[1], sV[9][0]); m89[3] = cmul(m8[1], sV[9][1]);
        #pragma unroll
        for (int p = 0; p < 8; p++){
            int u8i = (p >> 2) & 1;                 // selects m8 row (already xored t7)
            int u9  = ((p >> 1) ^ (p >> 2)) & 1;
            int u10 = (p ^ (p >> 1)) & 1;
            float2 t = cmul(m89[u8i*2 + u9], sV[10][u10]);
            float2 a0 = cmul(t, sV[11][p & 1]);          // slot0: u11 = p0
            float2 a1 = cmul(t, sV[11][(p & 1) ^ 1]);    // slot1: u11 = 1^p0
            X[p] = pk(a0.x, a1.x);
            Y[p] = pk(a0.y, a1.y);
        }
    }

    // Round: 3 p-wires (gA on p2 pairs, gB on p1, gC on p0) + slot gate cs
    auto round = [&](const u64* gA, const u64* gB, const u64* gC, const u64* cs){
        #pragma unroll
        for (int p = 0; p < 4; p++) gap2(gA, X[p], Y[p], X[p+4], Y[p+4]);
        gap2(gB, X[0], Y[0], X[2], Y[2]); gap2(gB, X[1], Y[1], X[3], Y[3]);
        gap2(gB, X[4], Y[4], X[6], Y[6]); gap2(gB, X[5], Y[5], X[7], Y[7]);
        gap2(gC, X[0], Y[0], X[1], Y[1]); gap2(gC, X[2], Y[2], X[3], Y[3]);
        gap2(gC, X[4], Y[4], X[5], Y[5]); gap2(gC, X[6], Y[6], X[7], Y[7]);
        u64 A = cs[0], B = cs[1], Ap = cs[2], Bp = cs[3], A2 = cs[4], B2 = cs[5];
        #pragma unroll
        for (int p = 0; p < 8; p++){
            u64 sX = swap_slots(X[p]);
            u64 sY = swap_slots(Y[p]);
            u64 nX = f2mul(A, X[p]); nX = f2fma(B,  sX, nX);
            nX = f2fma(Ap, Y[p], nX); nX = f2fma(Bp, sY, nX);
            u64 nY = f2mul(A, Y[p]); nY = f2fma(B,  sY, nY);
            nY = f2fma(A2, X[p], nY); nY = f2fma(B2, sX, nY);
            X[p] = nX; Y[p] = nY;
        }
    };

    // Canonical store: amp[(loc<<8) ^ tid ^ loc] for loc = p*2+slot
    auto ex_store = [&](){
        #pragma unroll
        for (int p = 0; p < 8; p++){
            float x0, x1, y0, y1;
            unpk(X[p], x0, x1); unpk(Y[p], y0, y1);
            int l0 = p*2, l1 = p*2 + 1;
            amp[(l0 << 8) ^ tid ^ l0] = make_float2(x0, y0);
            amp[(l1 << 8) ^ tid ^ l1] = make_float2(x1, y1);
        }
    };

    // X1/X4 (intra-warp): swap local quad <-> lane b3..b0 quad
    auto ex_gather_w = [&](){
        int base = warp*32 + (lane & 16);
        int locs = lane & 15;
        int xr = (locs << 8) ^ locs;
        #pragma unroll
        for (int p = 0; p < 8; p++){
            int t0 = base + (p << 1);
            float2 f0 = amp[xr ^ t0];
            float2 f1 = amp[xr ^ (t0 | 1)];
            X[p] = pk(f0.x, f1.x);
            Y[p] = pk(f0.y, f1.y);
        }
    };

    // X2/X5 (CTA): swap local quad <-> warp bits + lane b4
    auto ex_gather_c = [&](){
        int lane_base = (warp << 1) | ((lane >> 4) & 1);
        int locs = lane & 15;
        int xr = (locs << 8) ^ locs;
        #pragma unroll
        for (int p = 0; p < 8; p++){
            int t0 = (p << 5) + lane_base;
            float2 f0 = amp[xr ^ t0];
            float2 f1 = amp[xr ^ (t0 + 16)];
            X[p] = pk(f0.x, f1.x);
            Y[p] = pk(f0.y, f1.y);
        }
    };

    // X3 (CTA, sigma_2 folded): u_w = t_w ^ t_{w-1}, layout-preserving
    auto ex_gather_s = [&](){
        int lg   = (lane ^ (lane >> 1)) & 7;            // u5,u6,u7
        int u8   = ((warp >> 2) ^ lane) & 1;
        int u11  = ((lane >> 4) ^ warp) & 1;
        int wsrc = ((warp ^ (warp >> 1)) & 3) | (u8 << 2);
        int lane_base = (u11 << 4) | (lane & 8) | lg;   // bit3 = l3 (u4 at s=0)
        int tbase = wsrc*32 + lane_base;
        #pragma unroll
        for (int p = 0; p < 8; p++){
            int gp = (p ^ (p >> 1)) & 3;
            int lb = ((p >> 2) << 3) | (gp << 1);
            int loc0 = lb | (p & 1);
            int loc1 = lb | ((p & 1) ^ 1);
            float2 f0 = amp[((loc0 << 8) ^ loc0) ^ tbase];
            float2 f1 = amp[((loc1 << 8) ^ loc1) ^ (tbase ^ 8)];
            X[p] = pk(f0.x, f1.x);
            Y[p] = pk(f0.y, f1.y);
        }
    };

    // ======== 6 rounds, 5 exchanges ========
    round(sGp[0][8], sGp[0][9], sGp[0][10], sGs[0]);   // R1: L2 gates on 8,9,10,11
    ex_store(); __syncwarp(); ex_gather_w();            // X1 -> local {4,5,6,7}
    round(sGp[0][4], sGp[0][5], sGp[0][6], sGs[1]);    // R2
    ex_store(); __syncthreads(); ex_gather_c();         // X2 -> local {0,1,2,3}
    round(sGp[0][0], sGp[0][1], sGp[0][2], sGs[2]);    // R3 (layer 2 done)
    __syncthreads(); ex_store(); __syncthreads(); ex_gather_s();  // X3: sigma_2
    round(sGp[1][0], sGp[1][1], sGp[1][2], sGs[3]);    // R4: L3 gates on 0,1,2,3
    __syncthreads(); ex_store(); __syncwarp(); ex_gather_w();     // X4 -> {4,5,6,7}
    round(sGp[1][4], sGp[1][5], sGp[1][6], sGs[4]);    // R5
    ex_store(); __syncthreads(); ex_gather_c();         // X5 -> {8,9,10,11}
    round(sGp[1][8], sGp[1][9], sGp[1][10], sGs[5]);   // R6 (layer 3 done; layout = L1)

    // ---- Readout: sigma_3 folded via prefix parities (layout L1)
    int P = 0; float basec = 0.f;
    #pragma unroll
    for (int i = 0; i < 8; i++){
        P ^= (tid >> (7 - i)) & 1;
        basec += P ? -sHw[i] : sHw[i];
    }
    float h8 = sHw[8], h9 = sHw[9], h10 = sHw[10], h11 = sHw[11];
    u64 acc = pk(0.f, 0.f);
    #pragma unroll
    for (int p = 0; p < 8; p++){
        int P8  = P  ^ ((p >> 2) & 1);
        int P9  = P8 ^ ((p >> 1) & 1);
        int P10 = P9 ^ (p & 1);
        float cp = basec + (P8 ? -h8 : h8) + (P9 ? -h9 : h9) + (P10 ? -h10 : h10);
        float t11 = P10 ? -h11 : h11;
        u64 cpair = pk(cp + t11, cp - t11);
        u64 r2 = f2mul(X[p], X[p]);
        r2 = f2fma(Y[p], Y[p], r2);
        acc = f2fma(cpair, r2, acc);
    }
    float plo, phi; unpk(acc, plo, phi);
    float partial = plo + phi;
    #pragma unroll
    for (int off = 16; off; off >>= 1)
        partial += __shfl_down_sync(FULLMASK, partial, off);
    if (lane == 0) sRed[warp] = partial;
    __syncthreads();
    if (tid == 0){
        float s = hb[0];
        #pragma unroll
        for (int w = 0; w < 8; w++) s += sRed[w];
        out[b] = s;
    }
}

extern "C" void kernel_launch(void* const* d_in, const int* in_sizes, int n_in,
                              void* d_out, int out_size)
{
    const float* x      = (const float*)d_in[0];
    const float* params = (const float*)d_in[1];
    const float* hw     = (const float*)d_in[2];
    const float* hb     = (const float*)d_in[3];
    float* out = (float*)d_out;
    (void)in_sizes; (void)n_in;
    qsim_kernel<<<out_size, 256>>>(x, params, hw, hb, out);
}